// round 6
// baseline (speedup 1.0000x reference)
#include <cuda_runtime.h>
#include <cstdint>

// ---------------- problem constants ----------------
#define B_    16
#define C_    128
#define T_    16384
#define W_    2048      // wordnum = T/patch
#define P_    8
#define MIDC_ 128
#define CP_   1024      // MIDC * P

// ---------------- scratch (device globals; allocation-free rule) ----------------
__device__ float g_qr[(size_t)B_ * W_ * CP_];   // raw Q (pre-softmax) [b][w][i]
__device__ float g_q [(size_t)B_ * W_ * CP_];   // tf32 softmaxed Q    [b][w][i]
__device__ float g_kt[(size_t)B_ * CP_ * W_];   // K^T raw -> in-place tf32 softmax(K)^T [b][i][w]
__device__ float g_vt[(size_t)B_ * CP_ * W_];   // tf32 V^T            [b][i][w]
__device__ float g_kv[(size_t)B_ * CP_ * CP_];  // tf32 kv_mat^T       [b][i][j]
__device__ float g_at[(size_t)B_ * MIDC_ * T_]; // attn out fp32       [b][m][t]

// ---------------- helpers ----------------
__device__ __forceinline__ uint32_t smem_u32(const void* p) {
    uint32_t a;
    asm("{ .reg .u64 t; cvta.to.shared.u64 t, %1; cvt.u32.u64 %0, t; }"
        : "=r"(a) : "l"(p));
    return a;
}

__device__ __forceinline__ float to_tf32(float x) {
    uint32_t u;
    asm("cvt.rna.tf32.f32 %0, %1;" : "=r"(u) : "f"(x));
    return __uint_as_float(u);
}

#define LDSM4(r, addr)                                                        \
    asm volatile("ldmatrix.sync.aligned.m8n8.x4.shared.b16 {%0,%1,%2,%3}, [%4];" \
        : "=r"((r)[0]), "=r"((r)[1]), "=r"((r)[2]), "=r"((r)[3]) : "r"(addr))

__device__ __forceinline__ void mma_tf32(float* c, const uint32_t* a,
                                         uint32_t b0, uint32_t b1) {
    asm volatile(
        "mma.sync.aligned.m16n8k8.row.col.f32.tf32.tf32.f32 "
        "{%0,%1,%2,%3}, {%4,%5,%6,%7}, {%8,%9}, {%0,%1,%2,%3};"
        : "+f"(c[0]), "+f"(c[1]), "+f"(c[2]), "+f"(c[3])
        : "r"(a[0]), "r"(a[1]), "r"(a[2]), "r"(a[3]), "r"(b0), "r"(b1));
}

// =====================================================================
// Kernel A/B: grouped 5-tap conv as tf32 MMA (unchanged from R5).
// =====================================================================
#define CAPAD 172
#define CBPAD 260
#define CWPAD 33
#define CIPAD 260

template<int MOC, bool ISQ>
__global__ __launch_bounds__(256, 2)
void kConv(const float* __restrict__ inp, const float* __restrict__ wgt,
           const float* __restrict__ bias, const float* __restrict__ mask)
{
    extern __shared__ float sf[];
    float* As = sf;
    float* Bs = sf + MOC * CAPAD;

    const int tid  = threadIdx.x;
    const int lane = tid & 31, wid = tid >> 5;
    const int t0 = blockIdx.x * 256;
    const int w0 = blockIdx.x * 32;
    const int g  = blockIdx.y;
    const int b  = blockIdx.z;

    const float* Irow = inp + ((size_t)b * 128 + g * 32) * T_;
    const float* Arow = wgt + (size_t)g * MOC * 160;

    for (int idx = tid; idx < MOC * 40; idx += 256) {
        int row = idx / 40, c4 = idx - row * 40;
        float4 v = *(const float4*)(Arow + row * 160 + c4 * 4);
        v.x = to_tf32(v.x); v.y = to_tf32(v.y);
        v.z = to_tf32(v.z); v.w = to_tf32(v.w);
        *(float4*)&As[row * CAPAD + c4 * 4] = v;
    }

    auto load_chunk = [&](int ch) {
        uint32_t bb = smem_u32(Bs + (ch & 1) * 16 * CBPAD);
        #pragma unroll
        for (int it = 0; it < 4; it++) {
            int idx = tid + it * 256;
            int r = idx >> 6, c4 = (idx & 63) << 2;
            int k = ch * 16 + r;
            int ic = k / 5, kh = k - ic * 5;
            int t = t0 + c4 + (kh - 2) * 8;
            int tc = t < 0 ? 0 : (t > T_ - 4 ? T_ - 4 : t);
            int sz = (t >= 0 && t <= T_ - 4) ? 16 : 0;
            const float* src = Irow + (size_t)ic * T_ + tc;
            uint32_t dst = bb + (r * CBPAD + c4) * 4;
            asm volatile("cp.async.cg.shared.global [%0], [%1], 16, %2;"
                         :: "r"(dst), "l"(src), "r"(sz));
        }
        asm volatile("cp.async.commit_group;");
    };

    constexpr int MF = MOC / 16;
    float acc[MF][4][4];
    #pragma unroll
    for (int mi = 0; mi < MF; mi++)
        #pragma unroll
        for (int nb = 0; nb < 4; nb++)
            #pragma unroll
            for (int e = 0; e < 4; e++) acc[mi][nb][e] = 0.f;

    const int n_warp = wid * 32;
    const int a_row  = (lane < 16) ? lane : (lane - 16);
    const int a_koff = (lane < 16) ? 0 : 4;
    const int b_k    = lane & 3;
    const int b_n    = lane >> 2;
    const uint32_t As0 = smem_u32(As);

    load_chunk(0);
    __syncthreads();

    for (int ch = 0; ch < 10; ch++) {
        if (ch < 9) {
            load_chunk(ch + 1);
            asm volatile("cp.async.wait_group 1;");
        } else {
            asm volatile("cp.async.wait_group 0;");
        }
        __syncthreads();

        const float* Bb = Bs + (ch & 1) * 16 * CBPAD;
        #pragma unroll
        for (int ks = 0; ks < 2; ks++) {
            const int k0 = ks * 8;
            uint32_t ar[MF][4];
            #pragma unroll
            for (int mi = 0; mi < MF; mi++)
                LDSM4(ar[mi], As0 +
                    ((mi * 16 + a_row) * CAPAD + ch * 16 + k0 + a_koff) * 4);
            #pragma unroll
            for (int nb = 0; nb < 4; nb++) {
                const int n = n_warp + nb * 8 + b_n;
                uint32_t b0 = __float_as_uint(to_tf32(Bb[(k0 + b_k) * CBPAD + n]));
                uint32_t b1 = __float_as_uint(to_tf32(Bb[(k0 + 4 + b_k) * CBPAD + n]));
                #pragma unroll
                for (int mi = 0; mi < MF; mi++)
                    mma_tf32(acc[mi][nb], ar[mi], b0, b1);
            }
        }
        __syncthreads();
    }

    const int rg = lane >> 2;
    const int cg = (lane & 3) * 2;
    const float* bptr = bias + g * MOC;

    if (ISQ) {
        float* s2 = sf;
        #pragma unroll
        for (int mi = 0; mi < MF; mi++) {
            const int r0 = mi * 16 + rg, r1 = r0 + 8;
            const float bi0 = bptr[r0], bi1 = bptr[r1];
            #pragma unroll
            for (int nb = 0; nb < 4; nb++) {
                const int col = n_warp + nb * 8 + cg;
                const int w = col >> 3, p = col & 7;
                const float* c = acc[mi][nb];
                *(float2*)&s2[w * CIPAD + r0 * 8 + p] = make_float2(c[0] + bi0, c[1] + bi0);
                *(float2*)&s2[w * CIPAD + r1 * 8 + p] = make_float2(c[2] + bi1, c[3] + bi1);
            }
        }
        __syncthreads();
        const int w = tid >> 3, c64 = (tid & 7) * 32;
        float* dst = g_qr + ((size_t)b * W_ + w0 + w) * CP_ + g * 256 + c64;
        #pragma unroll
        for (int j = 0; j < 8; j++)
            *(float4*)(dst + j * 4) = *(const float4*)&s2[w * CIPAD + c64 + j * 4];
    } else {
        float* s2 = sf;
        const bool isK = (g < 2);
        const float* mrow = isK ?
            (mask + ((size_t)b * 128 + g * 64) * (size_t)T_ + t0) : nullptr;
        #pragma unroll
        for (int mi = 0; mi < MF; mi++) {
            const int r0 = mi * 16 + rg, r1 = r0 + 8;
            const float bi0 = bptr[r0], bi1 = bptr[r1];
            #pragma unroll
            for (int nb = 0; nb < 4; nb++) {
                const int col = n_warp + nb * 8 + cg;
                const int w = col >> 3, p = col & 7;
                const float* c = acc[mi][nb];
                float2 m0 = make_float2(0.f, 0.f), m1 = m0;
                if (isK) {
                    m0 = *(const float2*)(mrow + (size_t)r0 * T_ + col);
                    m1 = *(const float2*)(mrow + (size_t)r1 * T_ + col);
                }
                s2[(r0 * 8 + p)     * CWPAD + w] = c[0] + bi0 + m0.x;
                s2[(r0 * 8 + p + 1) * CWPAD + w] = c[1] + bi0 + m0.y;
                s2[(r1 * 8 + p)     * CWPAD + w] = c[2] + bi1 + m1.x;
                s2[(r1 * 8 + p + 1) * CWPAD + w] = c[3] + bi1 + m1.y;
            }
        }
        __syncthreads();
        #pragma unroll
        for (int h = 0; h < 2; h++) {
            const int i = tid + h * 256;
            float* drow = (isK ? g_kt : g_vt) +
                ((size_t)b * CP_ + (size_t)(g & 1) * 512 + i) * W_ + w0;
            #pragma unroll
            for (int j = 0; j < 8; j++) {
                float4 v;
                v.x = s2[i * CWPAD + j * 4 + 0];
                v.y = s2[i * CWPAD + j * 4 + 1];
                v.z = s2[i * CWPAD + j * 4 + 2];
                v.w = s2[i * CWPAD + j * 4 + 3];
                if (!isK) {
                    v.x = to_tf32(v.x); v.y = to_tf32(v.y);
                    v.z = to_tf32(v.z); v.w = to_tf32(v.w);
                }
                *(float4*)(drow + j * 4) = v;
            }
        }
    }
}

// =====================================================================
// Kernel C: row softmax of g_qr -> g_q tf32
// =====================================================================
__global__ __launch_bounds__(256, 4)
void kSoftQ()
{
    __shared__ float red[8];
    const int tid = threadIdx.x, lane = tid & 31, wrp = tid >> 5;
    const size_t off = ((size_t)blockIdx.y * W_ + blockIdx.x) * CP_;

    float4 v = *(const float4*)(g_qr + off + tid * 4);
    float mx = fmaxf(fmaxf(v.x, v.y), fmaxf(v.z, v.w));
    #pragma unroll
    for (int o = 16; o; o >>= 1)
        mx = fmaxf(mx, __shfl_xor_sync(0xffffffffu, mx, o));
    if (lane == 0) red[wrp] = mx;
    __syncthreads();
    float m = red[0];
    #pragma unroll
    for (int k = 1; k < 8; k++) m = fmaxf(m, red[k]);

    float4 e;
    e.x = __expf(v.x - m); e.y = __expf(v.y - m);
    e.z = __expf(v.z - m); e.w = __expf(v.w - m);
    float s = e.x + e.y + e.z + e.w;
    #pragma unroll
    for (int o = 16; o; o >>= 1)
        s += __shfl_xor_sync(0xffffffffu, s, o);
    __syncthreads();
    if (lane == 0) red[wrp] = s;
    __syncthreads();
    float tot = 0.f;
    #pragma unroll
    for (int k = 0; k < 8; k++) tot += red[k];
    float r = 1.f / tot;

    float4 o;
    o.x = to_tf32(e.x * r); o.y = to_tf32(e.y * r);
    o.z = to_tf32(e.z * r); o.w = to_tf32(e.w * r);
    *(float4*)(g_q + off + tid * 4) = o;
}

// =====================================================================
// Kernel D: per-row (i) softmax over w of g_kt, IN PLACE -> tf32
// =====================================================================
__global__ __launch_bounds__(256, 4)
void kStatK()
{
    __shared__ float red[8];
    const int tid = threadIdx.x, lane = tid & 31, wrp = tid >> 5;
    const size_t off = ((size_t)blockIdx.y * CP_ + blockIdx.x) * (size_t)W_;

    float4 v0 = *(const float4*)(g_kt + off + tid * 4);
    float4 v1 = *(const float4*)(g_kt + off + 1024 + tid * 4);
    float mx = fmaxf(fmaxf(fmaxf(v0.x, v0.y), fmaxf(v0.z, v0.w)),
                     fmaxf(fmaxf(v1.x, v1.y), fmaxf(v1.z, v1.w)));
    #pragma unroll
    for (int o = 16; o; o >>= 1)
        mx = fmaxf(mx, __shfl_xor_sync(0xffffffffu, mx, o));
    if (lane == 0) red[wrp] = mx;
    __syncthreads();
    float m = red[0];
    #pragma unroll
    for (int k = 1; k < 8; k++) m = fmaxf(m, red[k]);

    float4 e0, e1;
    e0.x = __expf(v0.x - m); e0.y = __expf(v0.y - m);
    e0.z = __expf(v0.z - m); e0.w = __expf(v0.w - m);
    e1.x = __expf(v1.x - m); e1.y = __expf(v1.y - m);
    e1.z = __expf(v1.z - m); e1.w = __expf(v1.w - m);
    float s = e0.x + e0.y + e0.z + e0.w + e1.x + e1.y + e1.z + e1.w;
    #pragma unroll
    for (int o = 16; o; o >>= 1)
        s += __shfl_xor_sync(0xffffffffu, s, o);
    __syncthreads();
    if (lane == 0) red[wrp] = s;
    __syncthreads();
    float tot = 0.f;
    #pragma unroll
    for (int k = 0; k < 8; k++) tot += red[k];
    float r = 1.f / tot;

    float4 o0, o1;
    o0.x = to_tf32(e0.x * r); o0.y = to_tf32(e0.y * r);
    o0.z = to_tf32(e0.z * r); o0.w = to_tf32(e0.w * r);
    o1.x = to_tf32(e1.x * r); o1.y = to_tf32(e1.y * r);
    o1.z = to_tf32(e1.z * r); o1.w = to_tf32(e1.w * r);
    *(float4*)(g_kt + off + tid * 4)        = o0;
    *(float4*)(g_kt + off + 1024 + tid * 4) = o1;
}

// =====================================================================
// Kernel E/F: tf32 mma.sync GEMM, 128x256 tile, 512 threads, BK=16,
// 4-stage cp.async. Warp grid 2(m) x 8(n), warp tile 64x32.
//   EPI==0: D1[i][j] = sum_w vt[i][w]*kt[j][w]  -> g_kv (tf32, kv_mat^T)
//   EPI==1: D2[w][i] = sum_j  q[w][j]*kv[i][j]  -> g_at scatter (fp32)
// =====================================================================
#define BKPAD   20
#define STG_SZ  (384 * BKPAD)   // floats per stage (A 128 + B 256 rows)

template<int KTOT, int MTOT, int EPI>
__global__ __launch_bounds__(512, 1)
void kGemmMMA()
{
    extern __shared__ float smemf[];
    const int tid  = threadIdx.x;
    const int lane = tid & 31, wid = tid >> 5;
    const int b  = blockIdx.z;
    const int n0 = blockIdx.x * 256;
    const int m0 = blockIdx.y * 128;

    const float* A  = (EPI == 0) ? g_vt : g_q;
    const float* Bp = (EPI == 0) ? g_kt : g_kv;

    const float* Ag = A  + (size_t)b * MTOT * KTOT + (size_t)m0 * KTOT;
    const float* Bg = Bp + (size_t)b * 1024 * KTOT + (size_t)n0 * KTOT;

    const uint32_t smem0 = smem_u32(smemf);
    const int NT = KTOT / 16;

    auto load_stage = [&](int s, int koff) {
        uint32_t sb = smem0 + (s & 3) * STG_SZ * 4;
        const float* Agt = Ag + koff;
        const float* Bgt = Bg + koff;
        #pragma unroll
        for (int it = 0; it < 3; it++) {
            int idx = tid + it * 512;           // 0..1535 float4s
            if (idx < 512) {                    // A: 128 rows x 4 chunks
                int r = idx >> 2, c = (idx & 3) * 4;
                asm volatile("cp.async.cg.shared.global [%0], [%1], 16;"
                             :: "r"(sb + (r * BKPAD + c) * 4),
                                "l"(Agt + (size_t)r * KTOT + c));
            } else {                            // B: 256 rows x 4 chunks
                int j = idx - 512;
                int r = j >> 2, c = (j & 3) * 4;
                asm volatile("cp.async.cg.shared.global [%0], [%1], 16;"
                             :: "r"(sb + ((128 + r) * BKPAD + c) * 4),
                                "l"(Bgt + (size_t)r * KTOT + c));
            }
        }
        asm volatile("cp.async.commit_group;");
    };

    #pragma unroll
    for (int s = 0; s < 3; s++) load_stage(s, s * 16);

    const int m_warp = (wid & 1) * 64;
    const int n_warp = (wid >> 1) * 32;

    float acc[4][4][4];
    #pragma unroll
    for (int mi = 0; mi < 4; mi++)
        #pragma unroll
        for (int nb = 0; nb < 4; nb++)
            #pragma unroll
            for (int e = 0; e < 4; e++) acc[mi][nb][e] = 0.f;

    const int a_row  = (lane < 16) ? lane : (lane - 16);
    const int a_koff = (lane < 16) ? 0 : 4;
    const int b_noff = (lane & 7) + ((lane >> 4) << 3);
    const int b_koff = ((lane >> 3) & 1) * 4;

    for (int t = 0; t < NT; t++) {
        asm volatile("cp.async.wait_group 2;");
        __syncthreads();

        if (t + 3 < NT) load_stage(t + 3, (t + 3) * 16);
        else            asm volatile("cp.async.commit_group;");

        const uint32_t As = smem0 + (t & 3) * STG_SZ * 4;
        const uint32_t Bs = As + 128 * BKPAD * 4;

        #pragma unroll
        for (int ks = 0; ks < 2; ks++) {
            const int k0 = ks * 8;
            uint32_t ar[4][4];
            #pragma unroll
            for (int mi = 0; mi < 4; mi++) {
                uint32_t addr = As +
                    ((m_warp + mi * 16 + a_row) * BKPAD + k0 + a_koff) * 4;
                LDSM4(ar[mi], addr);
            }
            uint32_t br[2][4];
            #pragma unroll
            for (int nb2 = 0; nb2 < 2; nb2++) {
                uint32_t addr = Bs +
                    ((n_warp + nb2 * 16 + b_noff) * BKPAD + k0 + b_koff) * 4;
                LDSM4(br[nb2], addr);
            }
            #pragma unroll
            for (int mi = 0; mi < 4; mi++)
                #pragma unroll
                for (int nb = 0; nb < 4; nb++)
                    mma_tf32(acc[mi][nb], ar[mi],
                             br[nb >> 1][(nb & 1) * 2],
                             br[nb >> 1][(nb & 1) * 2 + 1]);
        }
        __syncthreads();
    }

    const int rg = lane >> 2;
    const int cg = (lane & 3) * 2;
    #pragma unroll
    for (int mi = 0; mi < 4; mi++) {
        const int row = m0 + m_warp + mi * 16 + rg;
        #pragma unroll
        for (int nb = 0; nb < 4; nb++) {
            const int col = n0 + n_warp + nb * 8 + cg;
            const float* c = acc[mi][nb];
            if (EPI == 0) {
                float2 lo = make_float2(to_tf32(c[0]), to_tf32(c[1]));
                float2 hi = make_float2(to_tf32(c[2]), to_tf32(c[3]));
                *(float2*)&g_kv[((size_t)b * CP_ + row)     * CP_ + col] = lo;
                *(float2*)&g_kv[((size_t)b * CP_ + row + 8) * CP_ + col] = hi;
            } else {
                const int oc = col >> 3, p = col & 7;
                float* base = &g_at[((size_t)b * MIDC_ + oc) * T_];
                *(float2*)&base[(size_t)row * 8 + p]       = make_float2(c[0], c[1]);
                *(float2*)&base[(size_t)(row + 8) * 8 + p] = make_float2(c[2], c[3]);
            }
        }
    }
}

// =====================================================================
// Kernel G: conv1d via tf32 mma.sync (M=128 c, N=128 t, K=384).
// B built from a 6-row x 136-col cp.async staging tile per k-chunk
// (the 3 taps of each m-row share one load).
// =====================================================================
#define SROWS 6
#define SPAD  140
__global__ __launch_bounds__(256, 2)
void kConvMMA(const float* __restrict__ wOut, const float* __restrict__ bOut,
              float* __restrict__ out)
{
    __shared__ __align__(16) float As[2][128 * BKPAD];
    __shared__ __align__(16) float Bstg[2][SROWS * SPAD];

    const int tid  = threadIdx.x;
    const int lane = tid & 31, wid = tid >> 5;
    const int b  = blockIdx.y;
    const int t0 = blockIdx.x * 128;

    const float* Ab = &g_at[(size_t)b * MIDC_ * T_];

    auto load_chunk = [&](int ch) {
        const int buf = ch & 1;
        // A: wOut[:, ch*16 .. ch*16+16)  -> 512 float4
        uint32_t ab = smem_u32(&As[buf][0]);
        #pragma unroll
        for (int it = 0; it < 2; it++) {
            int idx = tid + it * 256;
            int r = idx >> 2, c = (idx & 3) * 4;
            asm volatile("cp.async.cg.shared.global [%0], [%1], 16;"
                         :: "r"(ab + (r * BKPAD + c) * 4),
                            "l"(wOut + (size_t)r * 384 + ch * 16 + c));
        }
        // B stage: rows m_base..m_base+5 of g_at, cols [t0-4, t0+132)
        const int m_base = (ch * 16) / 3;
        uint32_t bb = smem_u32(&Bstg[buf][0]);
        if (tid < 204) {
            int r = tid / 34, c4 = tid - r * 34;
            int t = t0 - 4 + c4 * 4;
            int tc = t < 0 ? 0 : (t > T_ - 4 ? T_ - 4 : t);
            int sz = (t >= 0 && t <= T_ - 4) ? 16 : 0;
            const float* src = Ab + (size_t)(m_base + r) * T_ + tc;
            asm volatile("cp.async.cg.shared.global [%0], [%1], 16, %2;"
                         :: "r"(bb + (r * SPAD + c4 * 4) * 4), "l"(src), "r"(sz));
        }
        asm volatile("cp.async.commit_group;");
    };

    const int m_warp = (wid & 1) * 64;
    const int n_warp = (wid >> 1) * 32;

    float acc[4][4][4];
    #pragma unroll
    for (int mi = 0; mi < 4; mi++)
        #pragma unroll
        for (int nb = 0; nb < 4; nb++)
            #pragma unroll
            for (int e = 0; e < 4; e++) acc[mi][nb][e] = 0.f;

    const int a_row  = (lane < 16) ? lane : (lane - 16);
    const int a_koff = (lane < 16) ? 0 : 4;
    const int b_k    = lane & 3;
    const int b_n    = lane >> 2;

    const uint32_t As0 = smem_u32(&As[0][0]);

    load_chunk(0);

    for (int ch = 0; ch < 24; ch++) {
        if (ch < 23) {
            load_chunk(ch + 1);
            asm volatile("cp.async.wait_group 1;");
        } else {
            asm volatile("cp.async.wait_group 0;");
        }
        __syncthreads();

        const int buf = ch & 1;
        const int m_base = (ch * 16) / 3;
        const uint32_t Asb = As0 + buf * (128 * BKPAD * 4);
        const float*   stg = &Bstg[buf][0];

        #pragma unroll
        for (int ks = 0; ks < 2; ks++) {
            const int k0 = ks * 8;
            uint32_t ar[4][4];
            #pragma unroll
            for (int mi = 0; mi < 4; mi++) {
                uint32_t addr = Asb +
                    ((m_warp + mi * 16 + a_row) * BKPAD + k0 + a_koff) * 4;
                LDSM4(ar[mi], addr);
            }
            // B fragments from stage
            const int kg0 = ch * 16 + k0 + b_k;
            const int kg1 = kg0 + 4;
            const int mr0 = kg0 / 3, kt0 = kg0 - mr0 * 3;
            const int mr1 = kg1 / 3, kt1 = kg1 - mr1 * 3;
            const float* row0 = stg + (mr0 - m_base) * SPAD + 3 + kt0;
            const float* row1 = stg + (mr1 - m_base) * SPAD + 3 + kt1;
            #pragma unroll
            for (int nb = 0; nb < 4; nb++) {
                const int n = n_warp + nb * 8 + b_n;
                uint32_t b0 = __float_as_uint(to_tf32(row0[n]));
                uint32_t b1 = __float_as_uint(to_tf32(row1[n]));
                #pragma unroll
                for (int mi = 0; mi < 4; mi++)
                    mma_tf32(acc[mi][nb], ar[mi], b0, b1);
            }
        }
        __syncthreads();
    }

    const int rg = lane >> 2;
    const int cg = (lane & 3) * 2;
    #pragma unroll
    for (int mi = 0; mi < 4; mi++) {
        const int row = m_warp + mi * 16 + rg;
        const float bi0 = __ldg(&bOut[row]);
        const float bi1 = __ldg(&bOut[row + 8]);
        float* r0 = out + ((size_t)b * 128 + row)     * T_ + t0;
        float* r1 = out + ((size_t)b * 128 + row + 8) * T_ + t0;
        #pragma unroll
        for (int nb = 0; nb < 4; nb++) {
            const int col = n_warp + nb * 8 + cg;
            const float* c = acc[mi][nb];
            *(float2*)(r0 + col) = make_float2(c[0] + bi0, c[1] + bi0);
            *(float2*)(r1 + col) = make_float2(c[2] + bi1, c[3] + bi1);
        }
    }
}

// =====================================================================
// launcher
// =====================================================================
extern "C" void kernel_launch(void* const* d_in, const int* in_sizes, int n_in,
                              void* d_out, int out_size)
{
    (void)in_sizes; (void)n_in; (void)out_size;
    const float* x    = (const float*)d_in[0];
    const float* cond = (const float*)d_in[1];
    const float* mask = (const float*)d_in[2];
    const float* wQ   = (const float*)d_in[3];
    const float* bQ   = (const float*)d_in[4];
    const float* wKV  = (const float*)d_in[5];
    const float* bKV  = (const float*)d_in[6];
    const float* wOut = (const float*)d_in[7];
    const float* bOut = (const float*)d_in[8];
    float* out = (float*)d_out;

    const size_t smQ  = (size_t)(32 * CAPAD + 2 * 16 * CBPAD) * sizeof(float);
    const size_t smKV = (size_t)(64 * CAPAD + 2 * 16 * CBPAD) * sizeof(float);
    const size_t smG  = (size_t)4 * STG_SZ * sizeof(float);   // 122880 B
    cudaFuncSetAttribute(kConv<32, true>,
                         cudaFuncAttributeMaxDynamicSharedMemorySize, (int)smQ);
    cudaFuncSetAttribute(kConv<64, false>,
                         cudaFuncAttributeMaxDynamicSharedMemorySize, (int)smKV);
    cudaFuncSetAttribute(kGemmMMA<2048, 1024, 0>,
                         cudaFuncAttributeMaxDynamicSharedMemorySize, (int)smG);
    cudaFuncSetAttribute(kGemmMMA<1024, 2048, 1>,
                         cudaFuncAttributeMaxDynamicSharedMemorySize, (int)smG);

    kConv<32, true ><<<dim3(T_ / 256, 4, B_), 256, smQ >>>(cond, wQ,  bQ,  nullptr);
    kConv<64, false><<<dim3(T_ / 256, 4, B_), 256, smKV>>>(x,    wKV, bKV, mask);
    kSoftQ<<<dim3(W_, B_), 256>>>();
    kStatK<<<dim3(CP_, B_), 256>>>();
    // GEMM1: D1[i][j] = sum_w vt[i][w] * kt[j][w]   (M=1024, N=1024, K=2048)
    kGemmMMA<2048, 1024, 0><<<dim3(CP_ / 256, CP_ / 128, B_), 512, smG>>>();
    // GEMM2: D2[w][i] = sum_j q[w][j] * kv[i][j]    (M=2048, N=1024, K=1024)
    kGemmMMA<1024, 2048, 1><<<dim3(CP_ / 256, W_ / 128, B_), 512, smG>>>();
    kConvMMA<<<dim3(T_ / 128, B_), 256>>>(wOut, bOut, out);
}